// round 8
// baseline (speedup 1.0000x reference)
#include <cuda_runtime.h>
#include <cuda_bf16.h>
#include <cstdint>

// Problem constants
#define BB 32
#define NN 400
#define TT 315
#define DD 512
#define HH 256
#define BT (BB*TT)          // 10080
#define NT (NN*TT)          // 126000
#define PNN 416             // NN padded to multiple of 32 (K-pad for bf16 GEMM)

// ---------------- scratch (static device globals; no allocation) -------------
__device__ float g_S[BB*NN*TT];         // [32][400][315] fp32
__device__ float g_txh[TT*HH];          // [315][256] fp32
__device__ float g_mv[2*BB];
__device__ float g_part[BB*4*2];
__device__ float g_H[BB*TT*HH];         // [32][315][256] fp32

// bf16 hi/lo operand planes (16B-aligned for cp.async)
__device__ __align__(256) __nv_bfloat16 g_fhi[BB*NN*DD], g_flo[BB*NN*DD];    // features
__device__ __align__(256) __nv_bfloat16 g_thi[TT*DD],    g_tlo[TT*DD];       // text
__device__ __align__(256) __nv_bfloat16 g_Ahi[DD*DD],    g_Alo[DD*DD];       // A
__device__ __align__(256) __nv_bfloat16 g_Whi[HH*2*DD],  g_Wlo[HH*2*DD];     // WhT
__device__ __align__(256) __nv_bfloat16 g_TAhi[TT*DD],   g_TAlo[TT*DD];      // TAT
__device__ __align__(256) __nv_bfloat16 g_F1hi[BB*HH*PNN], g_F1lo[BB*HH*PNN];// FWT
__device__ __align__(256) __nv_bfloat16 g_s1hi[BB*TT*PNN], g_s1lo[BB*TT*PNN];// s1T

// ================= helpers ===================================================
__device__ __forceinline__ uint32_t smem_to_u32(const void* p) {
    uint32_t a;
    asm("{ .reg .u64 t; cvta.to.shared.u64 t, %1; cvt.u32.u64 %0, t; }"
        : "=r"(a) : "l"(p));
    return a;
}

#define MBARRIER_INIT(addr, cnt) \
    asm volatile("mbarrier.init.shared.b64 [%0], %1;" \
        :: "r"((uint32_t)(addr)), "r"((uint32_t)(cnt)) : "memory")

#define MBAR_ARRIVE_REMOTE(local_mbar_addr, target_rank) \
    asm volatile("{\n\t.reg .b32 ra;\n\t" \
        "mapa.shared::cluster.u32 ra, %0, %1;\n\t" \
        "mbarrier.arrive.release.cluster.shared::cluster.b64 _, [ra];\n\t}" \
        :: "r"((uint32_t)(local_mbar_addr)), "r"((uint32_t)(target_rank)) : "memory")

#define MBAR_WAIT_CLUSTER(mbar_smem_addr, phase_parity) do { \
    uint32_t _mbar = (uint32_t)(mbar_smem_addr); \
    uint32_t _parity = (uint32_t)(phase_parity); \
    uint32_t _done; \
    asm volatile( \
        "{\n\t.reg .pred p;\n\t" \
        "mbarrier.try_wait.parity.acquire.cluster.shared::cta.b64 p, [%1], %2;\n\t" \
        "selp.b32 %0, 1, 0, p;\n\t}" \
        : "=r"(_done) : "r"(_mbar), "r"(_parity) : "memory"); \
    if (!_done) { \
        asm volatile( \
            "{\n\t.reg .pred P1;\n\t" \
            "WAIT_LOOP_%=:\n\t" \
            "mbarrier.try_wait.parity.acquire.cluster.shared::cta.b64 P1, [%0], %1, 0x989680;\n\t" \
            "@P1 bra.uni WAIT_DONE_%=;\n\t" \
            "bra.uni WAIT_LOOP_%=;\n\t" \
            "WAIT_DONE_%=:\n\t}" \
            :: "r"(_mbar), "r"(_parity) : "memory"); \
    } \
} while(0)

// split fp32 pair -> (hi bf16x2, lo bf16x2)
__device__ __forceinline__ void split2(float a0, float a1, uint32_t &h, uint32_t &l)
{
    asm("cvt.rn.satfinite.bf16x2.f32 %0, %1, %2;" : "=r"(h) : "f"(a1), "f"(a0));
    float h0 = __uint_as_float(h << 16);
    float h1 = __uint_as_float(h & 0xffff0000u);
    float l0 = a0 - h0;
    float l1 = a1 - h1;
    asm("cvt.rn.satfinite.bf16x2.f32 %0, %1, %2;" : "=r"(l) : "f"(l1), "f"(l0));
}

__device__ __forceinline__ void ldsm_x4(uint32_t* r, uint32_t addr) {
    asm volatile("ldmatrix.sync.aligned.m8n8.x4.shared.b16 {%0,%1,%2,%3}, [%4];"
        : "=r"(r[0]), "=r"(r[1]), "=r"(r[2]), "=r"(r[3]) : "r"(addr));
}

__device__ __forceinline__ void mma16816(float* c, const uint32_t* a, uint32_t b0, uint32_t b1) {
    asm volatile(
        "mma.sync.aligned.m16n8k16.row.col.f32.bf16.bf16.f32 "
        "{%0,%1,%2,%3}, {%4,%5,%6,%7}, {%8,%9}, {%0,%1,%2,%3};"
        : "+f"(c[0]), "+f"(c[1]), "+f"(c[2]), "+f"(c[3])
        : "r"(a[0]), "r"(a[1]), "r"(a[2]), "r"(a[3]), "r"(b0), "r"(b1));
}

__device__ __forceinline__ void cp16(uint32_t dst, const void* src) {
    asm volatile("cp.async.cg.shared.global [%0], [%1], 16;"
        :: "r"(dst), "l"(src) : "memory");
}
#define CP_COMMIT() asm volatile("cp.async.commit_group;" ::: "memory")
#define CP_WAIT2()  asm volatile("cp.async.wait_group 2;"  ::: "memory")

// ================= HMMA bf16-split NT GEMM, cp.async 3-stage pipeline ========
// C[m,n] = sum_k A[m,k]*B[n,k] with A,B given as bf16 hi/lo planes.
// K must be a multiple of 32 (pad planes with zeros).
// EPI 0: fp32 C.  EPI 1: C = relu(acc + aux[r*N+col] + bias[col]) fp32.
// EPI 2: write bf16 hi/lo planes Chi/Clo (cols [N,PN) zero-filled).

#define AS 80                  // smem bytes per row (64B data + 16B pad)
#define APL 10240              // 128*AS: one A plane
#define BPL 5120               // 64*AS:  one B plane
#define STG2 (2*APL + 2*BPL)   // 30720 per stage
#define HG_SMEM (3*STG2)       // 92160

template<int EPI>
__global__ void __launch_bounds__(256, 2) hgemm(
    int M, int N, int K,
    const __nv_bfloat16* __restrict__ Ahi, const __nv_bfloat16* __restrict__ Alo,
    int lda, long long sA,
    const __nv_bfloat16* __restrict__ Bhi, const __nv_bfloat16* __restrict__ Blo,
    int ldb, long long sB,
    float* __restrict__ C, int ldc, long long sC,
    __nv_bfloat16* __restrict__ Chi, __nv_bfloat16* __restrict__ Clo, int PN,
    const float* __restrict__ aux, const float* __restrict__ bias)
{
    extern __shared__ char smem[];
    uint32_t sb = smem_to_u32(smem);
    int tid = threadIdx.x, lane = tid & 31, wid = tid >> 5;

    Ahi += (long long)blockIdx.z * sA;  Alo += (long long)blockIdx.z * sA;
    Bhi += (long long)blockIdx.z * sB;  Blo += (long long)blockIdx.z * sB;
    if (EPI == 2) { Chi += (long long)blockIdx.z * sC; Clo += (long long)blockIdx.z * sC; }
    else          { C   += (long long)blockIdx.z * sC; }
    int m0 = blockIdx.y * 128, n0 = blockIdx.x * 64;

    // cp.async row/segment mapping (256 threads)
    const int arow = tid >> 2;          // 0..63 ; also handles arow+64
    const int sg   = (tid & 3);         // 16B segment within 64B row
    int ga1 = m0 + arow;       if (ga1 >= M) ga1 = M - 1;
    int ga2 = m0 + arow + 64;  if (ga2 >= M) ga2 = M - 1;
    int gb  = n0 + arow;       if (gb  >= N) gb  = N - 1;

    float acc[2][4][4];
    #pragma unroll
    for (int mi = 0; mi < 2; mi++)
        #pragma unroll
        for (int ni = 0; ni < 4; ni++)
            #pragma unroll
            for (int j = 0; j < 4; j++) acc[mi][ni][j] = 0.f;

    const int nst = K >> 5;

    auto issue = [&](int s) {
        int buf = s % 3;
        uint32_t bA = sb + buf * STG2;
        uint32_t bB = bA + 2 * APL;
        int k0 = s << 5;                    // k element base
        size_t ko = (size_t)(k0 + sg * 8);  // element offset within row
        // A hi plane
        cp16(bA + arow * AS + sg * 16,        Ahi + (size_t)ga1 * lda + ko);
        cp16(bA + (arow + 64) * AS + sg * 16, Ahi + (size_t)ga2 * lda + ko);
        // A lo plane
        cp16(bA + APL + arow * AS + sg * 16,        Alo + (size_t)ga1 * lda + ko);
        cp16(bA + APL + (arow + 64) * AS + sg * 16, Alo + (size_t)ga2 * lda + ko);
        // B planes
        cp16(bB + arow * AS + sg * 16,       Bhi + (size_t)gb * ldb + ko);
        cp16(bB + BPL + arow * AS + sg * 16, Blo + (size_t)gb * ldb + ko);
    };

    const int wm = (wid & 3) * 32;
    const int wn = (wid >> 2) * 32;
    const int lrow = lane & 15;
    const int lkof = (lane >> 4) * 8;

    auto compute = [&](int buf) {
        uint32_t baseAhi = sb + buf * STG2;
        uint32_t baseAlo = baseAhi + APL;
        uint32_t baseBhi = baseAhi + 2 * APL;
        uint32_t baseBlo = baseBhi + BPL;
        #pragma unroll
        for (int ks = 0; ks < 2; ks++) {
            uint32_t kb = (uint32_t)((ks * 16 + lkof) * 2);
            uint32_t ahi[2][4], alo[2][4], bhi[2][4], blo[2][4];
            #pragma unroll
            for (int mi = 0; mi < 2; mi++) {
                uint32_t off = (uint32_t)((wm + mi * 16 + lrow) * AS) + kb;
                ldsm_x4(ahi[mi], baseAhi + off);
                ldsm_x4(alo[mi], baseAlo + off);
            }
            #pragma unroll
            for (int np = 0; np < 2; np++) {
                uint32_t off = (uint32_t)((wn + np * 16 + lrow) * AS) + kb;
                ldsm_x4(bhi[np], baseBhi + off);
                ldsm_x4(blo[np], baseBlo + off);
            }
            #pragma unroll
            for (int mi = 0; mi < 2; mi++)
                #pragma unroll
                for (int ni = 0; ni < 4; ni++) {
                    int np = ni >> 1, sel = ni & 1;
                    uint32_t bh0 = bhi[np][sel], bh1 = bhi[np][2 + sel];
                    uint32_t bl0 = blo[np][sel], bl1 = blo[np][2 + sel];
                    mma16816(acc[mi][ni], ahi[mi], bh0, bh1);
                    mma16816(acc[mi][ni], ahi[mi], bl0, bl1);
                    mma16816(acc[mi][ni], alo[mi], bh0, bh1);
                }
        }
    };

    // 3-stage pipeline, always-commit group accounting
    issue(0); CP_COMMIT();
    issue(1); CP_COMMIT();
    issue(2); CP_COMMIT();
    for (int c = 0; c < nst; c++) {
        CP_WAIT2();
        __syncthreads();
        compute(c % 3);
        __syncthreads();
        if (c + 3 < nst) issue(c + 3);
        CP_COMMIT();
    }

    // epilogue
    #pragma unroll
    for (int mi = 0; mi < 2; mi++) {
        #pragma unroll
        for (int ni = 0; ni < 4; ni++) {
            int gm = m0 + wm + mi * 16 + (lane >> 2);
            int gn = n0 + wn + ni * 8 + (lane & 3) * 2;
            float* cc = acc[mi][ni];
            #pragma unroll
            for (int half = 0; half < 2; half++) {
                int r = gm + half * 8;
                if (r < M) {
                    #pragma unroll
                    for (int j = 0; j < 2; j++) {
                        int col = gn + j;
                        float v = cc[half * 2 + j];
                        if (EPI == 2) {
                            if (col < PN) {
                                float vv = (col < N) ? v : 0.f;
                                __nv_bfloat16 h = __float2bfloat16(vv);
                                __nv_bfloat16 l = __float2bfloat16(vv - __bfloat162float(h));
                                Chi[(size_t)r * ldc + col] = h;
                                Clo[(size_t)r * ldc + col] = l;
                            }
                        } else if (col < N) {
                            if (EPI == 1)
                                v = fmaxf(v + aux[(size_t)r * N + col] + bias[col], 0.f);
                            C[(size_t)r * ldc + col] = v;
                        }
                    }
                }
            }
        }
    }
}

// ---------------- operand converters -----------------------------------------
__global__ void split_pairs(const float2* __restrict__ src,
                            uint32_t* __restrict__ hi, uint32_t* __restrict__ lo,
                            int npairs)
{
    int i = blockIdx.x * 256 + threadIdx.x;
    if (i < npairs) {
        float2 v = src[i];
        uint32_t h, l;
        split2(v.x, v.y, h, l);
        hi[i] = h; lo[i] = l;
    }
}

// transpose + split: out planes [C][R] from in [R][C]
__global__ void transpose_split(const float* __restrict__ in,
                                __nv_bfloat16* __restrict__ hi,
                                __nv_bfloat16* __restrict__ lo, int R, int C)
{
    __shared__ float tile[32][33];
    int c0 = blockIdx.x * 32, r0 = blockIdx.y * 32;
    int x = threadIdx.x, y = threadIdx.y;
    #pragma unroll
    for (int j = 0; j < 32; j += 8) {
        int r = r0 + y + j, c = c0 + x;
        tile[y + j][x] = (r < R && c < C) ? in[(size_t)r * C + c] : 0.f;
    }
    __syncthreads();
    #pragma unroll
    for (int j = 0; j < 32; j += 8) {
        int c = c0 + y + j, r = r0 + x;
        if (c < C && r < R) {
            float v = tile[x][y + j];
            __nv_bfloat16 h = __float2bfloat16(v);
            __nv_bfloat16 l = __float2bfloat16(v - __bfloat162float(h));
            hi[(size_t)c * R + r] = h;
            lo[(size_t)c * R + r] = l;
        }
    }
}

// ---------------- instance-norm stats (2-stage) ------------------------------
__global__ void stats_part(const float* __restrict__ s, float* __restrict__ part)
{
    int x = blockIdx.x, b = blockIdx.y;
    const float4* p = (const float4*)(s + (size_t)b * NT + (size_t)x * 31500);
    float sum = 0.f, sq = 0.f;
    for (int i = threadIdx.x; i < 7875; i += 256) {
        float4 v = p[i];
        sum += v.x + v.y + v.z + v.w;
        sq  += v.x*v.x + v.y*v.y + v.z*v.z + v.w*v.w;
    }
    __shared__ float ssum[256], ssq[256];
    ssum[threadIdx.x] = sum; ssq[threadIdx.x] = sq;
    __syncthreads();
    for (int o = 128; o > 0; o >>= 1) {
        if (threadIdx.x < o) {
            ssum[threadIdx.x] += ssum[threadIdx.x + o];
            ssq[threadIdx.x]  += ssq[threadIdx.x + o];
        }
        __syncthreads();
    }
    if (threadIdx.x == 0) {
        part[(b * 4 + x) * 2 + 0] = ssum[0];
        part[(b * 4 + x) * 2 + 1] = ssq[0];
    }
}

__global__ void stats_comb(const float* __restrict__ part, float* __restrict__ mv)
{
    int b = threadIdx.x;
    if (b >= BB) return;
    float sum = 0.f, sq = 0.f;
    #pragma unroll
    for (int x = 0; x < 4; x++) {
        sum += part[(b * 4 + x) * 2 + 0];
        sq  += part[(b * 4 + x) * 2 + 1];
    }
    float m = sum / (float)NT;
    float var = sq / (float)NT - m * m;
    mv[2 * b] = m;
    mv[2 * b + 1] = rsqrtf(var + 1e-5f);
}

// ---------------- Sinkhorn v3 (R7, unchanged core) + bf16-plane epilogue -----
#define SK_THREADS 512
#define SK_NW 16
#define RPC 100
#define RTP 320
#define STP 321
#define JMAX 7

#define OFF_V     0
#define OFF_U     320
#define OFF_PACC  448
#define OFF_WACC  3748
#define OFF_RECV  8868
#define OFF_MBAR  11428
#define OFF_STAGE 11432
#define SK_FLOATS (OFF_STAGE + RPC*STP)
#define SK_SMEM  (SK_FLOATS*4)

__global__ void __cluster_dims__(4, 1, 1) __launch_bounds__(SK_THREADS, 1)
sinkhorn_kernel(
    const float* __restrict__ s, const float* __restrict__ gamma,
    const float* __restrict__ beta, const float* __restrict__ mv,
    __nv_bfloat16* __restrict__ s1hi, __nv_bfloat16* __restrict__ s1lo)
{
    extern __shared__ float sm[];
    float* vS    = sm + OFF_V;
    float* uS    = sm + OFF_U;
    float* pacc  = sm + OFF_PACC;
    float* wacc  = sm + OFF_WACC;
    float* recv  = sm + OFF_RECV;
    float* stage = sm + OFF_STAGE;
    uint32_t mbar = smem_to_u32(sm + OFF_MBAR);

    int b = blockIdx.x >> 2;
    int rank = blockIdx.x & 3;
    int tid = threadIdx.x, wid = tid >> 5, lane = tid & 31;
    int rowbase = rank * RPC;

    if (tid == 0) { MBARRIER_INIT(mbar, 4); MBARRIER_INIT(mbar + 8, 4); }
    for (int c = tid; c < RTP; c += SK_THREADS) vS[c] = (c < TT) ? 1.f : 0.f;
    __syncthreads();
    asm volatile("barrier.cluster.arrive.aligned;" ::: "memory");
    asm volatile("barrier.cluster.wait.aligned;" ::: "memory");

    float m = mv[2 * b], rstd = mv[2 * b + 1];
    float g = gamma[0] * rstd, be = beta[0];
    const float* sb = s + (size_t)b * NT;

    float2 E[JMAX][5];
    #pragma unroll
    for (int j = 0; j < JMAX; j++) {
        int r = wid + 16 * j;
        bool rv = (r < RPC);
        const float* srow = sb + (size_t)(rowbase + (rv ? r : 0)) * TT;
        #pragma unroll
        for (int k = 0; k < 5; k++) {
            int c = 64 * k + 2 * lane;
            E[j][k].x = (rv && c     < TT) ? __expf(g * (srow[c]     - m) + be) : 0.f;
            E[j][k].y = (rv && c + 1 < TT) ? __expf(g * (srow[c + 1] - m) + be) : 0.f;
        }
    }

    for (int it = 0; it < 100; ++it) {
        int par = it & 1;

        {
            float2 vv[5];
            #pragma unroll
            for (int k = 0; k < 5; k++)
                vv[k] = *(const float2*)&vS[64 * k + 2 * lane];
            #pragma unroll
            for (int j = 0; j < JMAX; j++) {
                int r = wid + 16 * j;
                if (r < RPC) {
                    float d0 = 0.f, d1 = 0.f;
                    #pragma unroll
                    for (int k = 0; k < 5; k++) {
                        d0 = fmaf(E[j][k].x, vv[k].x, d0);
                        d1 = fmaf(E[j][k].y, vv[k].y, d1);
                    }
                    pacc[r * 33 + lane] = d0 + d1;
                }
            }
        }
        __syncthreads();

        if (tid < RPC) {
            const float* pr = pacc + tid * 33;
            float s0 = 0.f, s1 = 0.f, s2 = 0.f, s3 = 0.f;
            #pragma unroll
            for (int i = 0; i < 32; i += 4) {
                s0 += pr[i]; s1 += pr[i + 1]; s2 += pr[i + 2]; s3 += pr[i + 3];
            }
            uS[tid] = __fdividef(1.f, (s0 + s1) + (s2 + s3));
        }
        __syncthreads();

        {
            float2 ca[5];
            #pragma unroll
            for (int k = 0; k < 5; k++) ca[k] = make_float2(0.f, 0.f);
            #pragma unroll
            for (int j = 0; j < JMAX; j++) {
                int r = wid + 16 * j;
                if (r < RPC) {
                    float uu = uS[r];
                    #pragma unroll
                    for (int k = 0; k < 5; k++) {
                        ca[k].x = fmaf(uu, E[j][k].x, ca[k].x);
                        ca[k].y = fmaf(uu, E[j][k].y, ca[k].y);
                    }
                }
            }
            #pragma unroll
            for (int k = 0; k < 5; k++)
                *(float2*)&wacc[wid * RTP + 64 * k + 2 * lane] = ca[k];
        }
        __syncthreads();

        for (int c = tid; c < TT; c += SK_THREADS) {
            float p = 0.f;
            #pragma unroll
            for (int w = 0; w < SK_NW; w++) p += wacc[w * RTP + c];
            float* dst = recv + (par * 4 + rank) * RTP + c;
            uint32_t laddr = (uint32_t)__cvta_generic_to_shared(dst);
            #pragma unroll
            for (int cta = 0; cta < 4; cta++) {
                uint32_t raddr;
                asm volatile("mapa.shared::cluster.u32 %0, %1, %2;"
                             : "=r"(raddr) : "r"(laddr), "r"(cta));
                asm volatile("st.shared::cluster.f32 [%0], %1;"
                             :: "r"(raddr), "f"(p) : "memory");
            }
        }
        asm volatile("fence.acq_rel.cluster;" ::: "memory");
        __syncthreads();
        if (tid == 0) {
            uint32_t lb = mbar + ((it & 1) << 3);
            #pragma unroll
            for (int cta = 0; cta < 4; cta++) MBAR_ARRIVE_REMOTE(lb, cta);
        }
        MBAR_WAIT_CLUSTER(mbar + ((it & 1) << 3), (it >> 1) & 1);

        for (int c = tid; c < TT; c += SK_THREADS) {
            float sum = recv[(par * 4 + 0) * RTP + c] + recv[(par * 4 + 1) * RTP + c]
                      + recv[(par * 4 + 2) * RTP + c] + recv[(par * 4 + 3) * RTP + c];
            vS[c] = __fdividef(1.f, sum);
        }
        __syncthreads();
    }

    // epilogue: stage = E*u, then transposed write of bf16 hi/lo planes * v
    #pragma unroll
    for (int j = 0; j < JMAX; j++) {
        int r = wid + 16 * j;
        if (r < RPC) {
            float uu = uS[r];
            #pragma unroll
            for (int k = 0; k < 5; k++) {
                int c = 64 * k + 2 * lane;
                stage[r * STP + c]     = E[j][k].x * uu;
                stage[r * STP + c + 1] = E[j][k].y * uu;
            }
        }
    }
    __syncthreads();
    size_t ob = (size_t)b * TT * PNN;
    for (int t = wid; t < TT; t += SK_NW) {
        float vt = vS[t];
        #pragma unroll
        for (int jj = 0; jj < 4; jj++) {
            int n = lane + 32 * jj;
            if (n < RPC) {
                float v = stage[n * STP + t] * vt;
                __nv_bfloat16 h = __float2bfloat16(v);
                __nv_bfloat16 l = __float2bfloat16(v - __bfloat162float(h));
                size_t o = ob + (size_t)t * PNN + rowbase + n;
                s1hi[o] = h; s1lo[o] = l;
            }
        }
        // zero-fill K-pad columns [NN, PNN)
        if (rank == 3 && lane < PNN - NN) {
            size_t o = ob + (size_t)t * PNN + NN + lane;
            s1hi[o] = __float2bfloat16(0.f);
            s1lo[o] = __float2bfloat16(0.f);
        }
    }
}

// ---------------- final head: pred[bt] = dot(h[bt,:], Wo) + bo ---------------
__global__ void final_head(const float* __restrict__ h, const float* __restrict__ Wo,
                           const float* __restrict__ bo, float* __restrict__ out)
{
    int row = blockIdx.x * 8 + (threadIdx.x >> 5);
    int lane = threadIdx.x & 31;
    if (row >= BT) return;
    const float* hr = h + (size_t)row * HH;
    float acc = 0.f;
    #pragma unroll
    for (int k = 0; k < HH / 32; k++)
        acc += hr[lane + 32 * k] * Wo[lane + 32 * k];
    #pragma unroll
    for (int o = 16; o > 0; o >>= 1)
        acc += __shfl_xor_sync(0xffffffffu, acc, o);
    if (lane == 0) out[row] = acc + bo[0];
}

// ---------------- launcher ---------------------------------------------------
extern "C" void kernel_launch(void* const* d_in, const int* in_sizes, int n_in,
                              void* d_out, int out_size)
{
    const float* features = (const float*)d_in[0];
    const float* text     = (const float*)d_in[1];
    const float* Amat     = (const float*)d_in[2];
    const float* gamma    = (const float*)d_in[3];
    const float* beta     = (const float*)d_in[4];
    const float* Wh       = (const float*)d_in[5];
    const float* bh       = (const float*)d_in[6];
    const float* Wo       = (const float*)d_in[7];
    const float* bo       = (const float*)d_in[8];
    float* out = (float*)d_out;

    float *S, *txh, *mv, *part, *Hb;
    __nv_bfloat16 *fhi, *flo, *thi, *tlo, *Ahi, *Alo, *Whi, *Wlo;
    __nv_bfloat16 *TAhi, *TAlo, *F1hi, *F1lo, *s1hi, *s1lo;
    cudaGetSymbolAddress((void**)&S,    g_S);
    cudaGetSymbolAddress((void**)&txh,  g_txh);
    cudaGetSymbolAddress((void**)&mv,   g_mv);
    cudaGetSymbolAddress((void**)&part, g_part);
    cudaGetSymbolAddress((void**)&Hb,   g_H);
    cudaGetSymbolAddress((void**)&fhi,  g_fhi);
    cudaGetSymbolAddress((void**)&flo,  g_flo);
    cudaGetSymbolAddress((void**)&thi,  g_thi);
    cudaGetSymbolAddress((void**)&tlo,  g_tlo);
    cudaGetSymbolAddress((void**)&Ahi,  g_Ahi);
    cudaGetSymbolAddress((void**)&Alo,  g_Alo);
    cudaGetSymbolAddress((void**)&Whi,  g_Whi);
    cudaGetSymbolAddress((void**)&Wlo,  g_Wlo);
    cudaGetSymbolAddress((void**)&TAhi, g_TAhi);
    cudaGetSymbolAddress((void**)&TAlo, g_TAlo);
    cudaGetSymbolAddress((void**)&F1hi, g_F1hi);
    cudaGetSymbolAddress((void**)&F1lo, g_F1lo);
    cudaGetSymbolAddress((void**)&s1hi, g_s1hi);
    cudaGetSymbolAddress((void**)&s1lo, g_s1lo);

    cudaFuncSetAttribute(sinkhorn_kernel,
                         cudaFuncAttributeMaxDynamicSharedMemorySize, SK_SMEM);
    cudaFuncSetAttribute(hgemm<0>,
                         cudaFuncAttributeMaxDynamicSharedMemorySize, HG_SMEM);
    cudaFuncSetAttribute(hgemm<1>,
                         cudaFuncAttributeMaxDynamicSharedMemorySize, HG_SMEM);
    cudaFuncSetAttribute(hgemm<2>,
                         cudaFuncAttributeMaxDynamicSharedMemorySize, HG_SMEM);

    // ---- operand conversions (stream 0, before fork) ----
    split_pairs<<<(BB*NN*DD/2 + 255)/256, 256>>>((const float2*)features,
        (uint32_t*)fhi, (uint32_t*)flo, BB*NN*DD/2);
    split_pairs<<<(TT*DD/2 + 255)/256, 256>>>((const float2*)text,
        (uint32_t*)thi, (uint32_t*)tlo, TT*DD/2);
    split_pairs<<<(DD*DD/2 + 255)/256, 256>>>((const float2*)Amat,
        (uint32_t*)Ahi, (uint32_t*)Alo, DD*DD/2);

    cudaStream_t st1;
    cudaStreamCreateWithFlags(&st1, cudaStreamNonBlocking);
    cudaEvent_t e0, e1;
    cudaEventCreateWithFlags(&e0, cudaEventDisableTiming);
    cudaEventCreateWithFlags(&e1, cudaEventDisableTiming);
    cudaEventRecord(e0, 0);
    cudaStreamWaitEvent(st1, e0, 0);

    // ---- side branch (st1): WhT planes -> txh, FWT planes ----
    transpose_split<<<dim3(8, 32, 1), dim3(32, 8), 0, st1>>>(Wh, Whi, Wlo, 2 * DD, HH);
    // txh[t][h] = sum_d text[t,d]*WhT[h][512+d]
    hgemm<0><<<dim3(4, 3, 1), 256, HG_SMEM, st1>>>(TT, HH, DD,
        thi, tlo, DD, 0,
        Whi + DD, Wlo + DD, 2 * DD, 0,
        txh, HH, 0, nullptr, nullptr, HH, nullptr, nullptr);
    // FWT[b][h][n] = sum_d WhT[h][d]*features[b][n][d]  -> bf16 planes (pad 416)
    hgemm<2><<<dim3(7, 2, BB), 256, HG_SMEM, st1>>>(HH, NN, DD,
        Whi, Wlo, 2 * DD, 0,
        fhi, flo, DD, (long long)NN * DD,
        nullptr, PNN, (long long)HH * PNN,
        F1hi, F1lo, PNN, nullptr, nullptr);
    cudaEventRecord(e1, st1);

    // ---- main branch (stream 0): TAT -> S -> stats -> sinkhorn ----
    // TAT[t][d] = sum_e text[t,e]*A[d,e] -> bf16 planes
    hgemm<2><<<dim3(8, 3, 1), 256, HG_SMEM>>>(TT, DD, DD,
        thi, tlo, DD, 0,
        Ahi, Alo, DD, 0,
        nullptr, DD, 0,
        TAhi, TAlo, DD, nullptr, nullptr);
    // S[bn][t] = sum_d features[bn,d]*TAT[t,d] -> fp32
    hgemm<0><<<dim3(5, 100, 1), 256, HG_SMEM>>>(BB * NN, TT, DD,
        fhi, flo, DD, 0,
        TAhi, TAlo, DD, 0,
        S, TT, 0, nullptr, nullptr, TT, nullptr, nullptr);
    stats_part<<<dim3(4, BB), 256>>>(S, part);
    stats_comb<<<1, 32>>>(part, mv);
    sinkhorn_kernel<<<BB * 4, SK_THREADS, SK_SMEM>>>(S, gamma, beta, mv, s1hi, s1lo);

    // join, then head
    cudaStreamWaitEvent(0, e1, 0);
    // H[b][t][h] = relu(sum_n s1T[b][t][n]*FWT[b][h][n] + txh[t][h] + bh[h])
    hgemm<1><<<dim3(4, 3, BB), 256, HG_SMEM>>>(TT, HH, PNN,
        s1hi, s1lo, PNN, (long long)TT * PNN,
        F1hi, F1lo, PNN, (long long)HH * PNN,
        Hb, HH, (long long)TT * HH,
        nullptr, nullptr, HH, txh, bh);
    final_head<<<1260, 256>>>(Hb, Wo, bo, out);

    cudaEventDestroy(e0);
    cudaEventDestroy(e1);
    cudaStreamDestroy(st1);
}

// round 10
// speedup vs baseline: 1.0504x; 1.0504x over previous
#include <cuda_runtime.h>
#include <cuda_bf16.h>
#include <cstdint>

// Problem constants
#define BB 32
#define NN 400
#define TT 315
#define DD 512
#define HH 256
#define BT (BB*TT)          // 10080
#define NT (NN*TT)          // 126000
#define PNN 416             // NN padded to multiple of 32 (K-pad for bf16 GEMM)

// ---------------- scratch (static device globals; no allocation) -------------
__device__ float g_S[BB*NN*TT];         // [32][400][315] fp32
__device__ float g_txh[TT*HH];          // [315][256] fp32
__device__ float g_H[BB*TT*HH];         // [32][315][256] fp32

// bf16 hi/lo operand planes (16B-aligned for cp.async)
__device__ __align__(256) __nv_bfloat16 g_fhi[BB*NN*DD], g_flo[BB*NN*DD];    // features
__device__ __align__(256) __nv_bfloat16 g_thi[TT*DD],    g_tlo[TT*DD];       // text
__device__ __align__(256) __nv_bfloat16 g_Ahi[DD*DD],    g_Alo[DD*DD];       // A
__device__ __align__(256) __nv_bfloat16 g_Whi[HH*2*DD],  g_Wlo[HH*2*DD];     // WhT
__device__ __align__(256) __nv_bfloat16 g_TAhi[TT*DD],   g_TAlo[TT*DD];      // TAT
__device__ __align__(256) __nv_bfloat16 g_F1hi[BB*HH*PNN], g_F1lo[BB*HH*PNN];// FWT
__device__ __align__(256) __nv_bfloat16 g_s1hi[BB*TT*PNN], g_s1lo[BB*TT*PNN];// s1T

// ================= helpers ===================================================
__device__ __forceinline__ uint32_t smem_to_u32(const void* p) {
    uint32_t a;
    asm("{ .reg .u64 t; cvta.to.shared.u64 t, %1; cvt.u32.u64 %0, t; }"
        : "=r"(a) : "l"(p));
    return a;
}

#define MBARRIER_INIT(addr, cnt) \
    asm volatile("mbarrier.init.shared.b64 [%0], %1;" \
        :: "r"((uint32_t)(addr)), "r"((uint32_t)(cnt)) : "memory")

#define MBAR_ARRIVE_REMOTE(local_mbar_addr, target_rank) \
    asm volatile("{\n\t.reg .b32 ra;\n\t" \
        "mapa.shared::cluster.u32 ra, %0, %1;\n\t" \
        "mbarrier.arrive.release.cluster.shared::cluster.b64 _, [ra];\n\t}" \
        :: "r"((uint32_t)(local_mbar_addr)), "r"((uint32_t)(target_rank)) : "memory")

#define MBAR_WAIT_CLUSTER(mbar_smem_addr, phase_parity) do { \
    uint32_t _mbar = (uint32_t)(mbar_smem_addr); \
    uint32_t _parity = (uint32_t)(phase_parity); \
    uint32_t _done; \
    asm volatile( \
        "{\n\t.reg .pred p;\n\t" \
        "mbarrier.try_wait.parity.acquire.cluster.shared::cta.b64 p, [%1], %2;\n\t" \
        "selp.b32 %0, 1, 0, p;\n\t}" \
        : "=r"(_done) : "r"(_mbar), "r"(_parity) : "memory"); \
    if (!_done) { \
        asm volatile( \
            "{\n\t.reg .pred P1;\n\t" \
            "WAIT_LOOP_%=:\n\t" \
            "mbarrier.try_wait.parity.acquire.cluster.shared::cta.b64 P1, [%0], %1, 0x989680;\n\t" \
            "@P1 bra.uni WAIT_DONE_%=;\n\t" \
            "bra.uni WAIT_LOOP_%=;\n\t" \
            "WAIT_DONE_%=:\n\t}" \
            :: "r"(_mbar), "r"(_parity) : "memory"); \
    } \
} while(0)

// split fp32 pair -> (hi bf16x2, lo bf16x2)
__device__ __forceinline__ void split2(float a0, float a1, uint32_t &h, uint32_t &l)
{
    asm("cvt.rn.satfinite.bf16x2.f32 %0, %1, %2;" : "=r"(h) : "f"(a1), "f"(a0));
    float h0 = __uint_as_float(h << 16);
    float h1 = __uint_as_float(h & 0xffff0000u);
    float l0 = a0 - h0;
    float l1 = a1 - h1;
    asm("cvt.rn.satfinite.bf16x2.f32 %0, %1, %2;" : "=r"(l) : "f"(l1), "f"(l0));
}

__device__ __forceinline__ void ldsm_x4(uint32_t* r, uint32_t addr) {
    asm volatile("ldmatrix.sync.aligned.m8n8.x4.shared.b16 {%0,%1,%2,%3}, [%4];"
        : "=r"(r[0]), "=r"(r[1]), "=r"(r[2]), "=r"(r[3]) : "r"(addr));
}

__device__ __forceinline__ void mma16816(float* c, const uint32_t* a, uint32_t b0, uint32_t b1) {
    asm volatile(
        "mma.sync.aligned.m16n8k16.row.col.f32.bf16.bf16.f32 "
        "{%0,%1,%2,%3}, {%4,%5,%6,%7}, {%8,%9}, {%0,%1,%2,%3};"
        : "+f"(c[0]), "+f"(c[1]), "+f"(c[2]), "+f"(c[3])
        : "r"(a[0]), "r"(a[1]), "r"(a[2]), "r"(a[3]), "r"(b0), "r"(b1));
}

__device__ __forceinline__ void cp16(uint32_t dst, const void* src) {
    asm volatile("cp.async.cg.shared.global [%0], [%1], 16;"
        :: "r"(dst), "l"(src) : "memory");
}
#define CP_COMMIT() asm volatile("cp.async.commit_group;" ::: "memory")
#define CP_WAIT1()  asm volatile("cp.async.wait_group 1;"  ::: "memory")

// ================= HMMA bf16-split NT GEMM, cp.async, 1 barrier/stage ========
// C[m,n] = sum_k A[m,k]*B[n,k] with A,B given as bf16 hi/lo planes.
// K must be a multiple of 32 (pad planes with zeros).
// EPI 0: fp32 C.  EPI 1: C = relu(acc + aux[r*N+col] + bias[col]) fp32.
// EPI 2: write bf16 hi/lo planes Chi/Clo (cols [N,PN) zero-filled).

#define AS 80                  // smem bytes per row (64B data + 16B pad)
#define APL 10240              // 128*AS: one A plane
#define BPL 5120               // 64*AS:  one B plane
#define STG2 (2*APL + 2*BPL)   // 30720 per stage
#define HG_SMEM (3*STG2)       // 92160

template<int EPI>
__global__ void __launch_bounds__(256, 2) hgemm(
    int M, int N, int K,
    const __nv_bfloat16* __restrict__ Ahi, const __nv_bfloat16* __restrict__ Alo,
    int lda, long long sA,
    const __nv_bfloat16* __restrict__ Bhi, const __nv_bfloat16* __restrict__ Blo,
    int ldb, long long sB,
    float* __restrict__ C, int ldc, long long sC,
    __nv_bfloat16* __restrict__ Chi, __nv_bfloat16* __restrict__ Clo, int PN,
    const float* __restrict__ aux, const float* __restrict__ bias)
{
    extern __shared__ char smem[];
    uint32_t sb = smem_to_u32(smem);
    int tid = threadIdx.x, lane = tid & 31, wid = tid >> 5;

    Ahi += (long long)blockIdx.z * sA;  Alo += (long long)blockIdx.z * sA;
    Bhi += (long long)blockIdx.z * sB;  Blo += (long long)blockIdx.z * sB;
    if (EPI == 2) { Chi += (long long)blockIdx.z * sC; Clo += (long long)blockIdx.z * sC; }
    else          { C   += (long long)blockIdx.z * sC; }
    int m0 = blockIdx.y * 128, n0 = blockIdx.x * 64;

    const int arow = tid >> 2;          // 0..63 ; also handles arow+64
    const int sg   = (tid & 3);         // 16B segment within 64B row
    int ga1 = m0 + arow;       if (ga1 >= M) ga1 = M - 1;
    int ga2 = m0 + arow + 64;  if (ga2 >= M) ga2 = M - 1;
    int gb  = n0 + arow;       if (gb  >= N) gb  = N - 1;

    float acc[2][4][4];
    #pragma unroll
    for (int mi = 0; mi < 2; mi++)
        #pragma unroll
        for (int ni = 0; ni < 4; ni++)
            #pragma unroll
            for (int j = 0; j < 4; j++) acc[mi][ni][j] = 0.f;

    const int nst = K >> 5;

    auto issue = [&](int s) {
        int buf = s % 3;
        uint32_t bA = sb + buf * STG2;
        uint32_t bB = bA + 2 * APL;
        int k0 = s << 5;
        size_t ko = (size_t)(k0 + sg * 8);
        cp16(bA + arow * AS + sg * 16,        Ahi + (size_t)ga1 * lda + ko);
        cp16(bA + (arow + 64) * AS + sg * 16, Ahi + (size_t)ga2 * lda + ko);
        cp16(bA + APL + arow * AS + sg * 16,        Alo + (size_t)ga1 * lda + ko);
        cp16(bA + APL + (arow + 64) * AS + sg * 16, Alo + (size_t)ga2 * lda + ko);
        cp16(bB + arow * AS + sg * 16,       Bhi + (size_t)gb * ldb + ko);
        cp16(bB + BPL + arow * AS + sg * 16, Blo + (size_t)gb * ldb + ko);
    };

    const int wm = (wid & 3) * 32;
    const int wn = (wid >> 2) * 32;
    const int lrow = lane & 15;
    const int lkof = (lane >> 4) * 8;

    auto compute = [&](int buf) {
        uint32_t baseAhi = sb + buf * STG2;
        uint32_t baseAlo = baseAhi + APL;
        uint32_t baseBhi = baseAhi + 2 * APL;
        uint32_t baseBlo = baseBhi + BPL;
        #pragma unroll
        for (int ks = 0; ks < 2; ks++) {
            uint32_t kb = (uint32_t)((ks * 16 + lkof) * 2);
            uint32_t ahi[2][4], alo[2][4], bhi[2][4], blo[2][4];
            #pragma unroll
            for (int mi = 0; mi < 2; mi++) {
                uint32_t off = (uint32_t)((wm + mi * 16 + lrow) * AS) + kb;
                ldsm_x4(ahi[mi], baseAhi + off);
                ldsm_x4(alo[mi], baseAlo + off);
            }
            #pragma unroll
            for (int np = 0; np < 2; np++) {
                uint32_t off = (uint32_t)((wn + np * 16 + lrow) * AS) + kb;
                ldsm_x4(bhi[np], baseBhi + off);
                ldsm_x4(blo[np], baseBlo + off);
            }
            #pragma unroll
            for (int mi = 0; mi < 2; mi++)
                #pragma unroll
                for (int ni = 0; ni < 4; ni++) {
                    int np = ni >> 1, sel = ni & 1;
                    uint32_t bh0 = bhi[np][sel], bh1 = bhi[np][2 + sel];
                    uint32_t bl0 = blo[np][sel], bl1 = blo[np][2 + sel];
                    mma16816(acc[mi][ni], ahi[mi], bh0, bh1);
                    mma16816(acc[mi][ni], ahi[mi], bl0, bl1);
                    mma16816(acc[mi][ni], alo[mi], bh0, bh1);
                }
        }
    };

    // 3 buffers, prefetch depth 2, ONE barrier per stage.
    // Hazard proof: compute(c) uses buf c%3; issue(c+2) writes (c+2)%3 != c%3;
    // the wrap write into c%3 happens at iter c+1 AFTER its top barrier, which
    // guarantees all threads finished compute(c).
    issue(0); CP_COMMIT();
    issue(1); CP_COMMIT();
    for (int c = 0; c < nst; c++) {
        CP_WAIT1();
        __syncthreads();
        compute(c % 3);
        if (c + 2 < nst) issue(c + 2);
        CP_COMMIT();
    }

    // epilogue
    #pragma unroll
    for (int mi = 0; mi < 2; mi++) {
        #pragma unroll
        for (int ni = 0; ni < 4; ni++) {
            int gm = m0 + wm + mi * 16 + (lane >> 2);
            int gn = n0 + wn + ni * 8 + (lane & 3) * 2;
            float* cc = acc[mi][ni];
            #pragma unroll
            for (int half = 0; half < 2; half++) {
                int r = gm + half * 8;
                if (r < M) {
                    #pragma unroll
                    for (int j = 0; j < 2; j++) {
                        int col = gn + j;
                        float v = cc[half * 2 + j];
                        if (EPI == 2) {
                            if (col < PN) {
                                float vv = (col < N) ? v : 0.f;
                                __nv_bfloat16 h = __float2bfloat16(vv);
                                __nv_bfloat16 l = __float2bfloat16(vv - __bfloat162float(h));
                                Chi[(size_t)r * ldc + col] = h;
                                Clo[(size_t)r * ldc + col] = l;
                            }
                        } else if (col < N) {
                            if (EPI == 1)
                                v = fmaxf(v + aux[(size_t)r * N + col] + bias[col], 0.f);
                            C[(size_t)r * ldc + col] = v;
                        }
                    }
                }
            }
        }
    }
}

// ---------------- fused operand splitter -------------------------------------
#define FPAIRS (BB*NN*DD/2)
#define TPAIRS (TT*DD/2)
#define APAIRS (DD*DD/2)
#define ALLPAIRS (FPAIRS + TPAIRS + APAIRS)

__global__ void split_all(
    const float2* __restrict__ f, const float2* __restrict__ t,
    const float2* __restrict__ A,
    uint32_t* __restrict__ fhi, uint32_t* __restrict__ flo,
    uint32_t* __restrict__ thi, uint32_t* __restrict__ tlo,
    uint32_t* __restrict__ Ahi, uint32_t* __restrict__ Alo)
{
    int i = blockIdx.x * 256 + threadIdx.x;
    float2 v; uint32_t *dh, *dl; int o;
    if (i < FPAIRS)                 { o = i;                   v = f[o]; dh = fhi; dl = flo; }
    else if (i < FPAIRS + TPAIRS)   { o = i - FPAIRS;          v = t[o]; dh = thi; dl = tlo; }
    else if (i < ALLPAIRS)          { o = i - FPAIRS - TPAIRS; v = A[o]; dh = Ahi; dl = Alo; }
    else return;
    uint32_t h, l;
    split2(v.x, v.y, h, l);
    dh[o] = h; dl[o] = l;
}

// transpose + split: out planes [C][R] from in [R][C]
__global__ void transpose_split(const float* __restrict__ in,
                                __nv_bfloat16* __restrict__ hi,
                                __nv_bfloat16* __restrict__ lo, int R, int C)
{
    __shared__ float tile[32][33];
    int c0 = blockIdx.x * 32, r0 = blockIdx.y * 32;
    int x = threadIdx.x, y = threadIdx.y;
    #pragma unroll
    for (int j = 0; j < 32; j += 8) {
        int r = r0 + y + j, c = c0 + x;
        tile[y + j][x] = (r < R && c < C) ? in[(size_t)r * C + c] : 0.f;
    }
    __syncthreads();
    #pragma unroll
    for (int j = 0; j < 32; j += 8) {
        int c = c0 + y + j, r = r0 + x;
        if (c < C && r < R) {
            float v = tile[x][y + j];
            __nv_bfloat16 h = __float2bfloat16(v);
            __nv_bfloat16 l = __float2bfloat16(v - __bfloat162float(h));
            hi[(size_t)c * R + r] = h;
            lo[(size_t)c * R + r] = l;
        }
    }
}

// ---------------- Sinkhorn v4: fused instance-norm stats + v3 core -----------
// 4-CTA cluster per batch; 512 threads; warp w holds rows {w+16j, j=0..6},
// lane l holds cols {64k+2l, 64k+2l+1, k=0..4}.
#define SK_THREADS 512
#define SK_NW 16
#define RPC 100
#define RTP 320
#define STP 321
#define JMAX 7

#define OFF_V     0
#define OFF_U     320
#define OFF_PACC  448                     // 100*33 = 3300 (also stats scratch 1024)
#define OFF_WACC  3748
#define OFF_RECV  8868                    // 2*4*RTP (stats exchange reuses [0..7])
#define OFF_MBAR  11428                   // 3 mbarriers = 24B (8B aligned)
#define OFF_STAGE 11440
#define SK_FLOATS (OFF_STAGE + RPC*STP)   // 43540
#define SK_SMEM  (SK_FLOATS*4)            // 174160 bytes

__global__ void __cluster_dims__(4, 1, 1) __launch_bounds__(SK_THREADS, 1)
sinkhorn_kernel(
    const float* __restrict__ s, const float* __restrict__ gamma,
    const float* __restrict__ beta,
    __nv_bfloat16* __restrict__ s1hi, __nv_bfloat16* __restrict__ s1lo)
{
    extern __shared__ float sm[];
    float* vS    = sm + OFF_V;
    float* uS    = sm + OFF_U;
    float* pacc  = sm + OFF_PACC;
    float* wacc  = sm + OFF_WACC;
    float* recv  = sm + OFF_RECV;
    float* stage = sm + OFF_STAGE;
    uint32_t mbar = smem_to_u32(sm + OFF_MBAR);

    int b = blockIdx.x >> 2;
    int rank = blockIdx.x & 3;
    int tid = threadIdx.x, wid = tid >> 5, lane = tid & 31;
    int rowbase = rank * RPC;

    if (tid == 0) {
        MBARRIER_INIT(mbar, 4);       // loop even
        MBARRIER_INIT(mbar + 8, 4);   // loop odd
        MBARRIER_INIT(mbar + 16, 4);  // stats
    }
    for (int c = tid; c < RTP; c += SK_THREADS) vS[c] = (c < TT) ? 1.f : 0.f;
    __syncthreads();
    asm volatile("barrier.cluster.arrive.aligned;" ::: "memory");
    asm volatile("barrier.cluster.wait.aligned;" ::: "memory");

    const float* sb = s + (size_t)b * NT;

    // ---- load RAW slab into E regs (invalid slots = 0) ----------------------
    float2 E[JMAX][5];
    #pragma unroll
    for (int j = 0; j < JMAX; j++) {
        int r = wid + 16 * j;
        bool rv = (r < RPC);
        const float* srow = sb + (size_t)(rowbase + (rv ? r : 0)) * TT;
        #pragma unroll
        for (int k = 0; k < 5; k++) {
            int c = 64 * k + 2 * lane;
            E[j][k].x = (rv && c     < TT) ? srow[c]     : 0.f;
            E[j][k].y = (rv && c + 1 < TT) ? srow[c + 1] : 0.f;
        }
    }

    // ---- fused instance-norm stats ------------------------------------------
    {
        float psum = 0.f, psq = 0.f;
        #pragma unroll
        for (int j = 0; j < JMAX; j++)
            #pragma unroll
            for (int k = 0; k < 5; k++) {
                psum += E[j][k].x + E[j][k].y;
                psq  += E[j][k].x * E[j][k].x + E[j][k].y * E[j][k].y;
            }
        pacc[tid] = psum; pacc[512 + tid] = psq;
        __syncthreads();
        for (int o = 256; o > 0; o >>= 1) {
            if (tid < o) {
                pacc[tid]       += pacc[tid + o];
                pacc[512 + tid] += pacc[512 + tid + o];
            }
            __syncthreads();
        }
        if (tid == 0) {
            float cs = pacc[0], cq = pacc[512];
            float* dst0 = recv + rank * 2;
            uint32_t la = (uint32_t)__cvta_generic_to_shared(dst0);
            #pragma unroll
            for (int cta = 0; cta < 4; cta++) {
                uint32_t ra;
                asm volatile("mapa.shared::cluster.u32 %0, %1, %2;"
                             : "=r"(ra) : "r"(la), "r"(cta));
                asm volatile("st.shared::cluster.f32 [%0], %1;" :: "r"(ra), "f"(cs) : "memory");
                asm volatile("st.shared::cluster.f32 [%0], %1;" :: "r"(ra + 4), "f"(cq) : "memory");
            }
            // arrive.release (same thread as the stores) on every CTA's stats mbar
            #pragma unroll
            for (int cta = 0; cta < 4; cta++) MBAR_ARRIVE_REMOTE(mbar + 16, cta);
        }
        MBAR_WAIT_CLUSTER(mbar + 16, 0);
    }
    float tsum = (recv[0] + recv[2]) + (recv[4] + recv[6]);
    float tsq  = (recv[1] + recv[3]) + (recv[5] + recv[7]);
    float m = tsum / (float)NT;
    float var = tsq / (float)NT - m * m;
    float rstd = rsqrtf(var + 1e-5f);
    float g = gamma[0] * rstd, be = beta[0];

    // ---- transform regs in place: E = exp(g*(s-m)+be), masked ---------------
    #pragma unroll
    for (int j = 0; j < JMAX; j++) {
        int r = wid + 16 * j;
        bool rv = (r < RPC);
        #pragma unroll
        for (int k = 0; k < 5; k++) {
            int c = 64 * k + 2 * lane;
            E[j][k].x = (rv && c     < TT) ? __expf(g * (E[j][k].x - m) + be) : 0.f;
            E[j][k].y = (rv && c + 1 < TT) ? __expf(g * (E[j][k].y - m) + be) : 0.f;
        }
    }
    __syncthreads();   // recv[0..7] consumed by all before loop overwrites

    for (int it = 0; it < 100; ++it) {
        int par = it & 1;

        {
            float2 vv[5];
            #pragma unroll
            for (int k = 0; k < 5; k++)
                vv[k] = *(const float2*)&vS[64 * k + 2 * lane];
            #pragma unroll
            for (int j = 0; j < JMAX; j++) {
                int r = wid + 16 * j;
                if (r < RPC) {
                    float d0 = 0.f, d1 = 0.f;
                    #pragma unroll
                    for (int k = 0; k < 5; k++) {
                        d0 = fmaf(E[j][k].x, vv[k].x, d0);
                        d1 = fmaf(E[j][k].y, vv[k].y, d1);
                    }
                    pacc[r * 33 + lane] = d0 + d1;
                }
            }
        }
        __syncthreads();

        if (tid < RPC) {
            const float* pr = pacc + tid * 33;
            float s0 = 0.f, s1 = 0.f, s2 = 0.f, s3 = 0.f;
            #pragma unroll
            for (int i = 0; i < 32; i += 4) {
                s0 += pr[i]; s1 += pr[i + 1]; s2 += pr[i + 2]; s3 += pr[i + 3];
            }
            uS[tid] = __fdividef(1.f, (s0 + s1) + (s2 + s3));
        }
        __syncthreads();

        {
            float2 ca[5];
            #pragma unroll
            for (int k = 0; k < 5; k++) ca[k] = make_float2(0.f, 0.f);
            #pragma unroll
            for (int j = 0; j < JMAX; j++) {
                int r = wid + 16 * j;
                if (r < RPC) {
                    float uu = uS[r];
                    #pragma unroll
                    for (int k = 0; k < 5; k++) {
                        ca[k].x = fmaf(uu, E[j][k].x, ca[k].x);
                        ca[k].y = fmaf(uu, E[j][k].y, ca[k].y);
                    }
                }
            }
            #pragma unroll
            for (int k = 0; k < 5; k++)
                *(float2*)&wacc[wid * RTP + 64 * k + 2 * lane] = ca[k];
        }
        __syncthreads();

        for (int c = tid; c < TT; c += SK_THREADS) {
            float p = 0.f;
            #pragma unroll
            for (int w = 0; w < SK_NW; w++) p += wacc[w * RTP + c];
            float* dst = recv + (par * 4 + rank) * RTP + c;
            uint32_t laddr = (uint32_t)__cvta_generic_to_shared(dst);
            #pragma unroll
            for (int cta = 0; cta < 4; cta++) {
                uint32_t raddr;
                asm volatile("mapa.shared::cluster.u32 %0, %1, %2;"
                             : "=r"(raddr) : "r"(laddr), "r"(cta));
                asm volatile("st.shared::cluster.f32 [%0], %1;"
                             :: "r"(raddr), "f"(p) : "memory");
            }
        }
        asm volatile("fence.acq_rel.cluster;" ::: "memory");
        __syncthreads();
        if (tid == 0) {
            uint32_t lb = mbar + ((it & 1) << 3);
            #pragma unroll
            for (int cta = 0; cta < 4; cta++) MBAR_ARRIVE_REMOTE(lb, cta);
        }
        MBAR_WAIT_CLUSTER(mbar + ((it & 1) << 3), (it >> 1) & 1);

        for (int c = tid; c < TT; c += SK_THREADS) {
            float sum = recv[(par * 4 + 0) * RTP + c] + recv[(par * 4 + 1) * RTP + c]
                      + recv[(par * 4 + 2) * RTP + c] + recv[(par * 4 + 3) * RTP + c];
            vS[c] = __fdividef(1.f, sum);
        }
        __syncthreads();
    }

    // epilogue: stage = E*u, then transposed write of bf16 hi/lo planes * v
    #pragma unroll
    for (int j = 0; j < JMAX; j++) {
        int r = wid + 16 * j;
        if (r < RPC) {
            float uu = uS[r];
            #pragma unroll
            for (int k = 0; k < 5; k++) {
                int c = 64 * k + 2 * lane;
                stage[r * STP + c]     = E[j][k].x * uu;
                stage[r * STP + c + 1] = E[j][k].y * uu;
            }
        }
    }
    __syncthreads();
    size_t ob = (size_t)b * TT * PNN;
    for (int t = wid; t < TT; t += SK_NW) {
        float vt = vS[t];
        #pragma unroll
        for (int jj = 0; jj < 4; jj++) {
            int n = lane + 32 * jj;
            if (n < RPC) {
                float v = stage[n * STP + t] * vt;
                __nv_bfloat16 h = __float2bfloat16(v);
                __nv_bfloat16 l = __float2bfloat16(v - __bfloat162float(h));
                size_t o = ob + (size_t)t * PNN + rowbase + n;
                s1hi[o] = h; s1lo[o] = l;
            }
        }
        if (rank == 3 && lane < PNN - NN) {
            size_t o = ob + (size_t)t * PNN + NN + lane;
            s1hi[o] = __float2bfloat16(0.f);
            s1lo[o] = __float2bfloat16(0.f);
        }
    }
}

// ---------------- final head: pred[bt] = dot(h[bt,:], Wo) + bo ---------------
__global__ void final_head(const float* __restrict__ h, const float* __restrict__ Wo,
                           const float* __restrict__ bo, float* __restrict__ out)
{
    int row = blockIdx.x * 8 + (threadIdx.x >> 5);
    int lane = threadIdx.x & 31;
    if (row >= BT) return;
    const float* hr = h + (size_t)row * HH;
    float acc = 0.f;
    #pragma unroll
    for (int k = 0; k < HH / 32; k++)
        acc += hr[lane + 32 * k] * Wo[lane + 32 * k];
    #pragma unroll
    for (int o = 16; o > 0; o >>= 1)
        acc += __shfl_xor_sync(0xffffffffu, acc, o);
    if (lane == 0) out[row] = acc + bo[0];
}

// ---------------- launcher ---------------------------------------------------
extern "C" void kernel_launch(void* const* d_in, const int* in_sizes, int n_in,
                              void* d_out, int out_size)
{
    const float* features = (const float*)d_in[0];
    const float* text     = (const float*)d_in[1];
    const float* Amat     = (const float*)d_in[2];
    const float* gamma    = (const float*)d_in[3];
    const float* beta     = (const float*)d_in[4];
    const float* Wh       = (const float*)d_in[5];
    const float* bh       = (const float*)d_in[6];
    const float* Wo       = (const float*)d_in[7];
    const float* bo       = (const float*)d_in[8];
    float* out = (float*)d_out;

    float *S, *txh, *Hb;
    __nv_bfloat16 *fhi, *flo, *thi, *tlo, *Ahi, *Alo, *Whi, *Wlo;
    __nv_bfloat16 *TAhi, *TAlo, *F1hi, *F1lo, *s1hi, *s1lo;
    cudaGetSymbolAddress((void**)&S,    g_S);
    cudaGetSymbolAddress((void**)&txh,  g_txh);
    cudaGetSymbolAddress((void**)&Hb,   g_H);
    cudaGetSymbolAddress((void**)&fhi,  g_fhi);
    cudaGetSymbolAddress((void**)&flo,  g_flo);
    cudaGetSymbolAddress((void**)&thi,  g_thi);
    cudaGetSymbolAddress((void**)&tlo,  g_tlo);
    cudaGetSymbolAddress((void**)&Ahi,  g_Ahi);
    cudaGetSymbolAddress((void**)&Alo,  g_Alo);
    cudaGetSymbolAddress((void**)&Whi,  g_Whi);
    cudaGetSymbolAddress((void**)&Wlo,  g_Wlo);
    cudaGetSymbolAddress((void**)&TAhi, g_TAhi);
    cudaGetSymbolAddress((void**)&TAlo, g_TAlo);
    cudaGetSymbolAddress((void**)&F1hi, g_F1hi);
    cudaGetSymbolAddress((void**)&F1lo, g_F1lo);
    cudaGetSymbolAddress((void**)&s1hi, g_s1hi);
    cudaGetSymbolAddress((void**)&s1lo, g_s1lo);

    cudaFuncSetAttribute(sinkhorn_kernel,
                         cudaFuncAttributeMaxDynamicSharedMemorySize, SK_SMEM);
    cudaFuncSetAttribute(hgemm<0>,
                         cudaFuncAttributeMaxDynamicSharedMemorySize, HG_SMEM);
    cudaFuncSetAttribute(hgemm<1>,
                         cudaFuncAttributeMaxDynamicSharedMemorySize, HG_SMEM);
    cudaFuncSetAttribute(hgemm<2>,
                         cudaFuncAttributeMaxDynamicSharedMemorySize, HG_SMEM);

    cudaStream_t st1;
    cudaStreamCreateWithFlags(&st1, cudaStreamNonBlocking);
    cudaEvent_t e0, e1;
    cudaEventCreateWithFlags(&e0, cudaEventDisableTiming);
    cudaEventCreateWithFlags(&e1, cudaEventDisableTiming);

    // launch idx 0: fused operand split
    split_all<<<(ALLPAIRS + 255)/256, 256>>>((const float2*)features,
        (const float2*)text, (const float2*)Amat,
        (uint32_t*)fhi, (uint32_t*)flo, (uint32_t*)thi, (uint32_t*)tlo,
        (uint32_t*)Ahi, (uint32_t*)Alo);
    cudaEventRecord(e0, 0);
    cudaStreamWaitEvent(st1, e0, 0);

    // idx 1: TAT[t][d] = sum_e text[t,e]*A[d,e] -> bf16 planes (main)
    hgemm<2><<<dim3(8, 3, 1), 256, HG_SMEM>>>(TT, DD, DD,
        thi, tlo, DD, 0,
        Ahi, Alo, DD, 0,
        nullptr, DD, 0,
        TAhi, TAlo, DD, nullptr, nullptr);
    // idx 2: S[bn][t] = sum_d features[bn,d]*TAT[t,d] -> fp32 (main)
    hgemm<0><<<dim3(5, 100, 1), 256, HG_SMEM>>>(BB * NN, TT, DD,
        fhi, flo, DD, 0,
        TAhi, TAlo, DD, 0,
        S, TT, 0, nullptr, nullptr, TT, nullptr, nullptr);
    // idx 3: WhT planes (side)
    transpose_split<<<dim3(8, 32, 1), dim3(32, 8), 0, st1>>>(Wh, Whi, Wlo, 2 * DD, HH);
    // idx 4: txh (side)
    hgemm<0><<<dim3(4, 3, 1), 256, HG_SMEM, st1>>>(TT, HH, DD,
        thi, tlo, DD, 0,
        Whi + DD, Wlo + DD, 2 * DD, 0,
        txh, HH, 0, nullptr, nullptr, HH, nullptr, nullptr);
    // idx 5: sinkhorn (main) — fused stats + 100 iters
    sinkhorn_kernel<<<BB * 4, SK_THREADS, SK_SMEM>>>(S, gamma, beta, s1hi, s1lo);
    // idx 6: FWT planes (side)
    hgemm<2><<<dim3(7, 2, BB), 256, HG_SMEM, st1>>>(HH, NN, DD,
        Whi, Wlo, 2 * DD, 0,
        fhi, flo, DD, (long long)NN * DD,
        nullptr, PNN, (long long)HH * PNN,
        F1hi, F1lo, PNN, nullptr, nullptr);
    cudaEventRecord(e1, st1);
    cudaStreamWaitEvent(0, e1, 0);

    // idx 7: H = relu(s1T·FWT^T + txh + bh)
    hgemm<1><<<dim3(4, 3, BB), 256, HG_SMEM>>>(TT, HH, PNN,
        s1hi, s1lo, PNN, (long long)TT * PNN,
        F1hi, F1lo, PNN, (long long)HH * PNN,
        Hb, HH, (long long)TT * HH,
        nullptr, nullptr, HH, txh, bh);
    // idx 8: head
    final_head<<<1260, 256>>>(Hb, Wo, bo, out);

    cudaEventDestroy(e0);
    cudaEventDestroy(e1);
    cudaStreamDestroy(st1);
}